// round 15
// baseline (speedup 1.0000x reference)
#include <cuda_runtime.h>
#include <stdint.h>

// ---------------------------------------------------------------------------
// LateralInhibition: per-batch top-k masking (B=8, N=4,194,304, k=419,430).
//
// ONE kernel, one wave (55 blocks/row x 8 rows = 440 blocks, 3/SM on 148 SMs):
//   stream: read 128MB + write 128MB fused, out[i] = (x > HI ? x : 0);
//           counts x>=LO; stages window candidates (LO<=x<=HI, ~14.7K/row,
//           ~267/block) in smem, publishes to global.
//   last block per row (arrive-counter):
//     fast select: fine hist over L2-hot candidates -> exact threshold +
//                  tie cutoff -> scatter-fixup of kept candidates.
//     fallback (any check fails; never on bench data): fully-general
//                  single-block exact select + full row rewrite.
//   row-state reset for next graph replay (barrier before reset - R13 fix).
// ---------------------------------------------------------------------------

#define NBATCH 8
#define CAP    262144
#define SCAP   1024
#define FINE   1024
#define MCAP   512
#define SBUF   8192         // 32KB smem union: staging / fine hist / fb hist
#define LO_F   1.272f       // window: ~+-12 sigma around thr ~ 1.2816+-0.00084
#define HI_F   1.292f

__device__ unsigned int g_cnt [NBATCH];     // window candidates per row
__device__ unsigned int g_gt  [NBATCH];     // count of x >= LO per row
__device__ unsigned int g_arrive[NBATCH];
__device__ unsigned int g_ovf [NBATCH];     // staging overflow flag per row
__device__ unsigned int g_ckey[NBATCH][CAP];
__device__ unsigned int g_cidx[NBATCH][CAP];

// monotonic float -> uint key (larger float => larger key)
__device__ __forceinline__ unsigned int f2k(float f) {
    unsigned int u = __float_as_uint(f);
    return u ^ (0x80000000u | (unsigned int)((int)u >> 31));
}

__global__ void __launch_bounds__(512, 3)
k_all(const float4* __restrict__ in, float4* __restrict__ out,
      int nvec, int k) {
    __shared__ unsigned int sbuf[SBUF];               // union scratch
    __shared__ unsigned int s_n, s_base, s_gt, s_last, s_bad;
    __shared__ unsigned int s_bsel, s_r, s_m, s_thr, s_extra, s_E, s_neq, s_cut;
    __shared__ unsigned int csum[32];
    unsigned int* skey = sbuf;            // [SCAP] streaming staging keys
    unsigned int* sidx = sbuf + SCAP;     // [SCAP] streaming staging idx
    const int b   = blockIdx.y;
    const int bd  = blockDim.x;
    const int tid = threadIdx.x;
    if (tid == 0) { s_n = 0; s_gt = 0; }
    __syncthreads();

    const float4* p = in  + (size_t)b * nvec;
    float4*       q = out + (size_t)b * nvec;
    int per_block = (nvec + gridDim.x - 1) / gridDim.x;
    int start = blockIdx.x * per_block;
    int end   = min(start + per_block, nvec);
    unsigned int mygt = 0;

    const unsigned int LOB = __float_as_uint(LO_F);
    const unsigned int WID = __float_as_uint(HI_F) - LOB;   // window width (bits)
    const unsigned int GTW = 0x7F800000u - LOB;             // [LO, +inf] width
    // t = bits(x)-LOB:  t<=GTW <=> x in [LO,+inf] (negatives/NaN wrap huge);
    //                   t<=WID <=> x in [LO,HI]   (window; candidate push).
    // out: keep x iff x > HI (certainly top-k since count(x>HI) < k);
    // zero otherwise (window elems fixed by last block's scatter).
    // hi = gt - n = count(x > HI) exactly.

    #define PA_VEC(v, vi) do {                                               \
        unsigned int t0 = __float_as_uint((v).x) - LOB;                      \
        unsigned int t1 = __float_as_uint((v).y) - LOB;                      \
        unsigned int t2 = __float_as_uint((v).z) - LOB;                      \
        unsigned int t3 = __float_as_uint((v).w) - LOB;                      \
        mygt += (t0 <= GTW) ? 1u : 0u;                                       \
        mygt += (t1 <= GTW) ? 1u : 0u;                                       \
        mygt += (t2 <= GTW) ? 1u : 0u;                                       \
        mygt += (t3 <= GTW) ? 1u : 0u;                                       \
        float4 o;                                                            \
        o.x = ((v).x > HI_F) ? (v).x : 0.0f;                                 \
        o.y = ((v).y > HI_F) ? (v).y : 0.0f;                                 \
        o.z = ((v).z > HI_F) ? (v).z : 0.0f;                                 \
        o.w = ((v).w > HI_F) ? (v).w : 0.0f;                                 \
        __stcs(&q[vi], o);                                                   \
        unsigned int mm = umin(umin(t0, t1), umin(t2, t3));                  \
        if (mm <= WID) {                                                     \
            unsigned int gb = (unsigned int)(vi) * 4u;                       \
            if (t0 <= WID) { unsigned int _p = atomicAdd(&s_n, 1u);          \
                if (_p < SCAP) { skey[_p] = t0 + LOB; sidx[_p] = gb; } }     \
            if (t1 <= WID) { unsigned int _p = atomicAdd(&s_n, 1u);          \
                if (_p < SCAP) { skey[_p] = t1 + LOB; sidx[_p] = gb + 1u; } }\
            if (t2 <= WID) { unsigned int _p = atomicAdd(&s_n, 1u);          \
                if (_p < SCAP) { skey[_p] = t2 + LOB; sidx[_p] = gb + 2u; } }\
            if (t3 <= WID) { unsigned int _p = atomicAdd(&s_n, 1u);          \
                if (_p < SCAP) { skey[_p] = t3 + LOB; sidx[_p] = gb + 3u; } }\
        }                                                                    \
    } while (0)

    int i = start + tid;
    for (; i + 3 * bd < end; i += 4 * bd) {
        float4 v0 = p[i];
        float4 v1 = p[i + bd];
        float4 v2 = p[i + 2 * bd];
        float4 v3 = p[i + 3 * bd];
        PA_VEC(v0, i);
        PA_VEC(v1, i + bd);
        PA_VEC(v2, i + 2 * bd);
        PA_VEC(v3, i + 3 * bd);
    }
    for (; i < end; i += bd) {
        float4 v = p[i];
        PA_VEC(v, i);
    }
    #undef PA_VEC

    #pragma unroll
    for (int o = 16; o > 0; o >>= 1) mygt += __shfl_down_sync(0xFFFFFFFFu, mygt, o);
    if ((tid & 31) == 0) atomicAdd(&s_gt, mygt);
    __syncthreads();
    if (tid == 0) {
        if (s_n > SCAP) g_ovf[b] = 1;        // staging overflow -> row fallback
        unsigned int m = min(s_n, (unsigned int)SCAP);
        atomicAdd(&g_gt[b], s_gt);
        s_base = atomicAdd(&g_cnt[b], m);
        s_n = m;
    }
    __syncthreads();
    for (unsigned int j = tid; j < s_n; j += bd) {
        unsigned int gp = s_base + j;
        if (gp < CAP) { g_ckey[b][gp] = skey[j]; g_cidx[b][gp] = sidx[j]; }
    }
    __syncthreads();
    __threadfence();
    if (tid == 0)
        s_last = (atomicAdd(&g_arrive[b], 1u) == gridDim.x - 1u) ? 1u : 0u;
    __syncthreads();
    if (!s_last) return;

    // ============ last block of this row: select + fixup + reset ===========
    __threadfence();
    const unsigned int ncnt = g_cnt[b];
    const unsigned int gt   = g_gt[b];
    const unsigned int ovf  = g_ovf[b];
    const unsigned int uk   = (unsigned int)k;
    __syncthreads();   // all threads captured counters BEFORE reset (R13 fix)
    if (tid == 0) { g_cnt[b] = 0; g_gt[b] = 0; g_arrive[b] = 0; g_ovf[b] = 0; }
    if (tid == 0)
        s_bad = (ovf || !((ncnt <= CAP) && (ncnt <= gt) &&
                          (gt - ncnt < uk) && (gt >= uk))) ? 1u : 0u;
    __syncthreads();

    if (!s_bad) {
        // ---------------- fast select on window candidates -----------------
        const unsigned int n    = ncnt;
        const unsigned int rank = uk - (gt - n);   // 1-based rank in window
        const unsigned int LOB2 = __float_as_uint(LO_F);
        unsigned int* h   = sbuf;          // [FINE] fine hist
        unsigned int* aux = sbuf + FINE;   // boundary keys / eq indices

        for (int j = tid; j < FINE; j += bd) h[j] = 0;
        if (tid == 0) { s_m = 0; s_neq = 0; s_cut = 0xFFFFFFFFu;
                        s_thr = 0; s_extra = 0; s_E = 0; }
        __syncthreads();
        // window bit-span ~0x2A000; >>8 = 256-ulp bins, <=672 <= FINE.
        for (unsigned int j = tid; j < n; j += bd)
            atomicAdd(&h[(g_ckey[b][j] - LOB2) >> 8], 1u);
        __syncthreads();
        if (tid < 32) {
            unsigned int s = 0;
            #pragma unroll
            for (int t = 0; t < 32; t++) s += h[tid * 32 + t];
            csum[tid] = s;
        }
        __syncthreads();
        if (tid == 0) {
            unsigned int cum = 0;
            int c = 31;
            for (; c > 0; c--) {
                if (cum + csum[c] >= rank) break;
                cum += csum[c];
            }
            int bsel = c * 32;
            for (int d = c * 32 + 31; d >= c * 32; d--) {
                if (cum + h[d] >= rank) { bsel = d; break; }
                cum += h[d];
            }
            s_bsel = (unsigned int)bsel;
            s_r    = rank - cum;
        }
        __syncthreads();
        const unsigned int bsel = s_bsel, r = s_r;
        for (unsigned int j = tid; j < n; j += bd) {
            unsigned int uv = g_ckey[b][j];
            if (((uv - LOB2) >> 8) == bsel) {
                unsigned int pp = atomicAdd(&s_m, 1u);
                if (pp < MCAP) aux[pp] = uv;
            }
        }
        __syncthreads();
        unsigned int m = s_m;
        if (m > MCAP) { if (tid == 0) s_bad = 1; }
        __syncthreads();
        if (!s_bad) {
            for (unsigned int j = tid; j < m; j += bd) {
                unsigned int x = aux[j], cg = 0, ce = 0;
                for (unsigned int t = 0; t < m; t++) {
                    unsigned int y = aux[t];
                    cg += (y > x); ce += (y == x);
                }
                if (cg < r && r <= cg + ce) { s_thr = x; s_extra = r - cg; s_E = ce; }
            }
            __syncthreads();
            const unsigned int thr = s_thr, extra = s_extra, E = s_E;
            if (extra < E) {   // tie-break: extra-th smallest index among equals
                for (unsigned int j = tid; j < n; j += bd) {
                    if (g_ckey[b][j] == thr) {
                        unsigned int pp = atomicAdd(&s_neq, 1u);
                        if (pp < SCAP) aux[pp] = g_cidx[b][j];
                    }
                }
                __syncthreads();
                unsigned int ne = s_neq;
                if (ne > SCAP) { if (tid == 0) s_bad = 1; }
                __syncthreads();
                if (!s_bad) {
                    for (unsigned int j = tid; j < ne; j += bd) {
                        unsigned int me = aux[j], c2 = 0;
                        for (unsigned int t = 0; t < ne; t++) c2 += (aux[t] <= me);
                        if (c2 == extra) s_cut = me;
                    }
                }
                __syncthreads();
            }
            if (!s_bad) {
                // scatter-fixup: flip kept window candidates from 0 to value
                const unsigned int thrk = thr | 0x80000000u;  // f2k, positive
                const unsigned int cut  = s_cut;
                float* orow = (float*)q;
                for (unsigned int j = tid; j < n; j += bd) {
                    unsigned int key = g_ckey[b][j];
                    unsigned int kf  = key | 0x80000000u;
                    unsigned int idx = g_cidx[b][j];
                    if (kf > thrk || (kf == thrk && idx <= cut))
                        orow[idx] = __uint_as_float(key);
                }
                return;
            }
        }
    }

    // ---------- per-row FULLY GENERAL fallback (single block; slow) --------
    // Never taken on the bench input; exact for any input.
    {
        __syncthreads();
        unsigned int* sh = sbuf;   // [SBUF]=8192 bins
        for (int j = tid; j < SBUF; j += bd) sh[j] = 0;
        if (tid == 0) { s_n = 0; s_neq = 0; s_cut = 0xFFFFFFFFu; }
        __syncthreads();
        for (int j = tid; j < nvec; j += bd) {
            float4 v = p[j];
            atomicAdd(&sh[f2k(v.x) >> 19], 1u);
            atomicAdd(&sh[f2k(v.y) >> 19], 1u);
            atomicAdd(&sh[f2k(v.z) >> 19], 1u);
            atomicAdd(&sh[f2k(v.w) >> 19], 1u);
        }
        __syncthreads();
        if (tid == 0) {
            unsigned int cum = 0;
            for (int j = SBUF - 1; j >= 0; j--) {
                unsigned int c = sh[j];
                if (cum + c >= uk) { s_bsel = (unsigned int)j; s_r = uk - cum; break; }
                cum += c;
            }
        }
        __syncthreads();
        const unsigned int pref = s_bsel;
        for (int j = tid; j < nvec; j += bd) {
            float4 v = p[j];
            unsigned int kk[4] = { f2k(v.x), f2k(v.y), f2k(v.z), f2k(v.w) };
            #pragma unroll
            for (int jj = 0; jj < 4; jj++) {
                if ((kk[jj] >> 19) == pref) {
                    unsigned int pos = atomicAdd(&s_n, 1u);
                    if (pos < CAP) {
                        g_ckey[b][pos] = kk[jj];
                        g_cidx[b][pos] = (unsigned int)j * 4u + (unsigned int)jj;
                    }
                }
            }
        }
        __syncthreads();
        const unsigned int n2 = min(s_n, (unsigned int)CAP);
        unsigned int fixedval = 0, fixedmask = 0;
        if (tid == 0) { s_m = s_r; s_E = 0; }   // s_m = running rank
        __syncthreads();
        const int shifts[3] = { 11, 3, 0 };
        const int widths[3] = { 8, 8, 3 };
        for (int rr = 0; rr < 3; rr++) {
            const int s = shifts[rr];
            const unsigned int mw = (1u << widths[rr]) - 1u;
            for (int j = tid; j < 256; j += bd) sh[j] = 0;
            __syncthreads();
            for (unsigned int j = tid; j < n2; j += bd) {
                unsigned int low = g_ckey[b][j] & 0x7FFFFu;
                if ((low & fixedmask) == fixedval)
                    atomicAdd(&sh[(low >> s) & mw], 1u);
            }
            __syncthreads();
            if (tid == 0) {
                unsigned int cum = 0, rank = s_m, sel = 0;
                for (int d = (int)mw; d >= 0; d--) {
                    unsigned int c = sh[d];
                    if (cum + c >= rank) { sel = (unsigned int)d; s_m = rank - cum; s_E = c; break; }
                    cum += c;
                }
                s_thr = sel;   // broadcast digit via s_thr
            }
            __syncthreads();
            fixedval  |= s_thr << s;
            fixedmask |= mw    << s;
            __syncthreads();
        }
        const unsigned int thr   = (pref << 19) | fixedval;
        const unsigned int extra = s_m;
        const unsigned int E     = s_E;
        if (extra < E) {
            unsigned int* eq = sh;
            for (unsigned int j = tid; j < n2; j += bd) {
                if (g_ckey[b][j] == thr) {
                    unsigned int pos = atomicAdd(&s_neq, 1u);
                    if (pos < SBUF) eq[pos] = g_cidx[b][j];
                }
            }
            __syncthreads();
            unsigned int ne = min(s_neq, (unsigned int)SBUF);
            for (unsigned int j = tid; j < ne; j += bd) {
                unsigned int me = eq[j], c2 = 0;
                for (unsigned int t = 0; t < ne; t++) c2 += (eq[t] <= me);
                if (c2 == extra) s_cut = me;
            }
            __syncthreads();
        }
        const unsigned int cut = s_cut;
        // full rewrite of this row
        for (int j = tid; j < nvec; j += bd) {
            float4 v = p[j];
            unsigned int base = (unsigned int)j * 4u;
            unsigned int k0 = f2k(v.x), k1 = f2k(v.y), k2 = f2k(v.z), k3 = f2k(v.w);
            float4 o;
            o.x = (k0 > thr || (k0 == thr && base + 0u <= cut)) ? v.x : 0.0f;
            o.y = (k1 > thr || (k1 == thr && base + 1u <= cut)) ? v.y : 0.0f;
            o.z = (k2 > thr || (k2 == thr && base + 2u <= cut)) ? v.z : 0.0f;
            o.w = (k3 > thr || (k3 == thr && base + 3u <= cut)) ? v.w : 0.0f;
            q[j] = o;
        }
    }
}

// ============================== HOST =======================================

extern "C" void kernel_launch(void* const* d_in, const int* in_sizes, int n_in,
                              void* d_out, int out_size) {
    (void)n_in; (void)out_size;
    const int total = in_sizes[0];           // 33,554,432
    const int N     = total / NBATCH;        // 4,194,304
    int k = (int)((double)N * 0.1);          // 419,430
    if (k < 1) k = 1;
    const int nvec = N / 4;                  // 1,048,576 float4 per row

    const float4* in  = (const float4*)d_in[0];
    float4*       out = (float4*)d_out;

    // one wave: 55 blocks/row x 8 rows = 440 blocks <= 148 SMs x 3/SM = 444
    dim3 gA(55, NBATCH);
    k_all<<<gA, 512>>>(in, out, nvec, k);
}

// round 16
// speedup vs baseline: 1.1632x; 1.1632x over previous
#include <cuda_runtime.h>
#include <stdint.h>

// ---------------------------------------------------------------------------
// LateralInhibition: per-batch top-k masking (B=8, N=4,194,304, k=419,430).
//
// ONE kernel, 256 blocks/row x 8 rows = 2048 blocks (fastest measured
// streaming geometry):
//   stream: read 128MB (__ldcs) + write 128MB (__stcs) fused,
//           out[i] = (x > HI ? x : 0); counts x>=LO; stages window
//           candidates (LO<=x<=HI, ~9.6K/row, ~37/block).
//   last block per row (arrive-counter):
//     fast select: fine hist over L2-hot candidates -> exact threshold +
//                  tie cutoff -> scatter-fixup of kept candidates.
//     fallback (any check fails; never on bench data): fully-general
//                  single-block exact select + full row rewrite.
//   row-state reset for next graph replay (barrier before reset - R13 fix).
// ---------------------------------------------------------------------------

#define NBATCH 8
#define CAP    262144
#define SCAP   1024
#define FINE   1024
#define MCAP   512
#define SBUF   8192         // 32KB smem union: staging / fine hist / fb hist
#define LO_F   1.275f       // window: ~+-7.7 sigma around thr ~ 1.28155+-0.00084
#define HI_F   1.288f

__device__ unsigned int g_cnt [NBATCH];     // window candidates per row
__device__ unsigned int g_gt  [NBATCH];     // count of x >= LO per row
__device__ unsigned int g_arrive[NBATCH];
__device__ unsigned int g_ovf [NBATCH];     // staging overflow flag per row
__device__ unsigned int g_ckey[NBATCH][CAP];
__device__ unsigned int g_cidx[NBATCH][CAP];

// monotonic float -> uint key (larger float => larger key)
__device__ __forceinline__ unsigned int f2k(float f) {
    unsigned int u = __float_as_uint(f);
    return u ^ (0x80000000u | (unsigned int)((int)u >> 31));
}

__global__ void __launch_bounds__(512, 3)
k_all(const float4* __restrict__ in, float4* __restrict__ out,
      int nvec, int k) {
    __shared__ unsigned int sbuf[SBUF];               // union scratch
    __shared__ unsigned int s_n, s_base, s_gt, s_last, s_bad;
    __shared__ unsigned int s_bsel, s_r, s_m, s_thr, s_extra, s_E, s_neq, s_cut;
    __shared__ unsigned int csum[32];
    unsigned int* skey = sbuf;            // [SCAP] streaming staging keys
    unsigned int* sidx = sbuf + SCAP;     // [SCAP] streaming staging idx
    const int b   = blockIdx.y;
    const int bd  = blockDim.x;
    const int tid = threadIdx.x;
    if (tid == 0) { s_n = 0; s_gt = 0; }
    __syncthreads();

    const float4* p = in  + (size_t)b * nvec;
    float4*       q = out + (size_t)b * nvec;
    int per_block = (nvec + gridDim.x - 1) / gridDim.x;
    int start = blockIdx.x * per_block;
    int end   = min(start + per_block, nvec);
    unsigned int mygt = 0;

    const unsigned int LOB = __float_as_uint(LO_F);
    const unsigned int WID = __float_as_uint(HI_F) - LOB;   // window width (bits)
    const unsigned int GTW = 0x7F800000u - LOB;             // [LO, +inf] width
    // t = bits(x)-LOB:  t<=GTW <=> x in [LO,+inf] (negatives/NaN wrap huge);
    //                   t<=WID <=> x in [LO,HI]   (window; candidate push).
    // out: keep x iff x > HI (certainly top-k since count(x>HI) < k);
    // zero otherwise (window elems fixed by last block's scatter).
    // hi = gt - n = count(x > HI) exactly.

    #define PA_VEC(v, vi) do {                                               \
        unsigned int t0 = __float_as_uint((v).x) - LOB;                      \
        unsigned int t1 = __float_as_uint((v).y) - LOB;                      \
        unsigned int t2 = __float_as_uint((v).z) - LOB;                      \
        unsigned int t3 = __float_as_uint((v).w) - LOB;                      \
        mygt += (t0 <= GTW) ? 1u : 0u;                                       \
        mygt += (t1 <= GTW) ? 1u : 0u;                                       \
        mygt += (t2 <= GTW) ? 1u : 0u;                                       \
        mygt += (t3 <= GTW) ? 1u : 0u;                                       \
        float4 o;                                                            \
        o.x = ((v).x > HI_F) ? (v).x : 0.0f;                                 \
        o.y = ((v).y > HI_F) ? (v).y : 0.0f;                                 \
        o.z = ((v).z > HI_F) ? (v).z : 0.0f;                                 \
        o.w = ((v).w > HI_F) ? (v).w : 0.0f;                                 \
        __stcs(&q[vi], o);                                                   \
        unsigned int mm = umin(umin(t0, t1), umin(t2, t3));                  \
        if (mm <= WID) {                                                     \
            unsigned int gb = (unsigned int)(vi) * 4u;                       \
            if (t0 <= WID) { unsigned int _p = atomicAdd(&s_n, 1u);          \
                if (_p < SCAP) { skey[_p] = t0 + LOB; sidx[_p] = gb; } }     \
            if (t1 <= WID) { unsigned int _p = atomicAdd(&s_n, 1u);          \
                if (_p < SCAP) { skey[_p] = t1 + LOB; sidx[_p] = gb + 1u; } }\
            if (t2 <= WID) { unsigned int _p = atomicAdd(&s_n, 1u);          \
                if (_p < SCAP) { skey[_p] = t2 + LOB; sidx[_p] = gb + 2u; } }\
            if (t3 <= WID) { unsigned int _p = atomicAdd(&s_n, 1u);          \
                if (_p < SCAP) { skey[_p] = t3 + LOB; sidx[_p] = gb + 3u; } }\
        }                                                                    \
    } while (0)

    int i = start + tid;
    for (; i + 3 * bd < end; i += 4 * bd) {
        float4 v0 = __ldcs(&p[i]);
        float4 v1 = __ldcs(&p[i + bd]);
        float4 v2 = __ldcs(&p[i + 2 * bd]);
        float4 v3 = __ldcs(&p[i + 3 * bd]);
        PA_VEC(v0, i);
        PA_VEC(v1, i + bd);
        PA_VEC(v2, i + 2 * bd);
        PA_VEC(v3, i + 3 * bd);
    }
    for (; i < end; i += bd) {
        float4 v = __ldcs(&p[i]);
        PA_VEC(v, i);
    }
    #undef PA_VEC

    #pragma unroll
    for (int o = 16; o > 0; o >>= 1) mygt += __shfl_down_sync(0xFFFFFFFFu, mygt, o);
    if ((tid & 31) == 0) atomicAdd(&s_gt, mygt);
    __syncthreads();
    if (tid == 0) {
        if (s_n > SCAP) g_ovf[b] = 1;        // staging overflow -> row fallback
        unsigned int m = min(s_n, (unsigned int)SCAP);
        atomicAdd(&g_gt[b], s_gt);
        s_base = atomicAdd(&g_cnt[b], m);
        s_n = m;
    }
    __syncthreads();
    for (unsigned int j = tid; j < s_n; j += bd) {
        unsigned int gp = s_base + j;
        if (gp < CAP) { g_ckey[b][gp] = skey[j]; g_cidx[b][gp] = sidx[j]; }
    }
    __syncthreads();
    __threadfence();
    if (tid == 0)
        s_last = (atomicAdd(&g_arrive[b], 1u) == gridDim.x - 1u) ? 1u : 0u;
    __syncthreads();
    if (!s_last) return;

    // ============ last block of this row: select + fixup + reset ===========
    __threadfence();
    const unsigned int ncnt = g_cnt[b];
    const unsigned int gt   = g_gt[b];
    const unsigned int ovf  = g_ovf[b];
    const unsigned int uk   = (unsigned int)k;
    __syncthreads();   // all threads captured counters BEFORE reset (R13 fix)
    if (tid == 0) { g_cnt[b] = 0; g_gt[b] = 0; g_arrive[b] = 0; g_ovf[b] = 0; }
    if (tid == 0)
        s_bad = (ovf || !((ncnt <= CAP) && (ncnt <= gt) &&
                          (gt - ncnt < uk) && (gt >= uk))) ? 1u : 0u;
    __syncthreads();

    if (!s_bad) {
        // ---------------- fast select on window candidates -----------------
        const unsigned int n    = ncnt;
        const unsigned int rank = uk - (gt - n);   // 1-based rank in window
        const unsigned int LOB2 = __float_as_uint(LO_F);
        unsigned int* h   = sbuf;          // [FINE] fine hist
        unsigned int* aux = sbuf + FINE;   // boundary keys / eq indices

        for (int j = tid; j < FINE; j += bd) h[j] = 0;
        if (tid == 0) { s_m = 0; s_neq = 0; s_cut = 0xFFFFFFFFu;
                        s_thr = 0; s_extra = 0; s_E = 0; }
        __syncthreads();
        // window bit-span ~0x15000; >>8 = 256-ulp bins, <=FINE bins.
        for (unsigned int j = tid; j < n; j += bd)
            atomicAdd(&h[(g_ckey[b][j] - LOB2) >> 8], 1u);
        __syncthreads();
        if (tid < 32) {
            unsigned int s = 0;
            #pragma unroll
            for (int t = 0; t < 32; t++) s += h[tid * 32 + t];
            csum[tid] = s;
        }
        __syncthreads();
        if (tid == 0) {
            unsigned int cum = 0;
            int c = 31;
            for (; c > 0; c--) {
                if (cum + csum[c] >= rank) break;
                cum += csum[c];
            }
            int bsel = c * 32;
            for (int d = c * 32 + 31; d >= c * 32; d--) {
                if (cum + h[d] >= rank) { bsel = d; break; }
                cum += h[d];
            }
            s_bsel = (unsigned int)bsel;
            s_r    = rank - cum;
        }
        __syncthreads();
        const unsigned int bsel = s_bsel, r = s_r;
        for (unsigned int j = tid; j < n; j += bd) {
            unsigned int uv = g_ckey[b][j];
            if (((uv - LOB2) >> 8) == bsel) {
                unsigned int pp = atomicAdd(&s_m, 1u);
                if (pp < MCAP) aux[pp] = uv;
            }
        }
        __syncthreads();
        unsigned int m = s_m;
        if (m > MCAP) { if (tid == 0) s_bad = 1; }
        __syncthreads();
        if (!s_bad) {
            for (unsigned int j = tid; j < m; j += bd) {
                unsigned int x = aux[j], cg = 0, ce = 0;
                for (unsigned int t = 0; t < m; t++) {
                    unsigned int y = aux[t];
                    cg += (y > x); ce += (y == x);
                }
                if (cg < r && r <= cg + ce) { s_thr = x; s_extra = r - cg; s_E = ce; }
            }
            __syncthreads();
            const unsigned int thr = s_thr, extra = s_extra, E = s_E;
            if (extra < E) {   // tie-break: extra-th smallest index among equals
                for (unsigned int j = tid; j < n; j += bd) {
                    if (g_ckey[b][j] == thr) {
                        unsigned int pp = atomicAdd(&s_neq, 1u);
                        if (pp < SCAP) aux[pp] = g_cidx[b][j];
                    }
                }
                __syncthreads();
                unsigned int ne = s_neq;
                if (ne > SCAP) { if (tid == 0) s_bad = 1; }
                __syncthreads();
                if (!s_bad) {
                    for (unsigned int j = tid; j < ne; j += bd) {
                        unsigned int me = aux[j], c2 = 0;
                        for (unsigned int t = 0; t < ne; t++) c2 += (aux[t] <= me);
                        if (c2 == extra) s_cut = me;
                    }
                }
                __syncthreads();
            }
            if (!s_bad) {
                // scatter-fixup: flip kept window candidates from 0 to value
                const unsigned int thrk = thr | 0x80000000u;  // f2k, positive
                const unsigned int cut  = s_cut;
                float* orow = (float*)q;
                for (unsigned int j = tid; j < n; j += bd) {
                    unsigned int key = g_ckey[b][j];
                    unsigned int kf  = key | 0x80000000u;
                    unsigned int idx = g_cidx[b][j];
                    if (kf > thrk || (kf == thrk && idx <= cut))
                        orow[idx] = __uint_as_float(key);
                }
                return;
            }
        }
    }

    // ---------- per-row FULLY GENERAL fallback (single block; slow) --------
    // Never taken on the bench input; exact for any input.
    {
        __syncthreads();
        unsigned int* sh = sbuf;   // [SBUF]=8192 bins
        for (int j = tid; j < SBUF; j += bd) sh[j] = 0;
        if (tid == 0) { s_n = 0; s_neq = 0; s_cut = 0xFFFFFFFFu; }
        __syncthreads();
        for (int j = tid; j < nvec; j += bd) {
            float4 v = p[j];
            atomicAdd(&sh[f2k(v.x) >> 19], 1u);
            atomicAdd(&sh[f2k(v.y) >> 19], 1u);
            atomicAdd(&sh[f2k(v.z) >> 19], 1u);
            atomicAdd(&sh[f2k(v.w) >> 19], 1u);
        }
        __syncthreads();
        if (tid == 0) {
            unsigned int cum = 0;
            for (int j = SBUF - 1; j >= 0; j--) {
                unsigned int c = sh[j];
                if (cum + c >= uk) { s_bsel = (unsigned int)j; s_r = uk - cum; break; }
                cum += c;
            }
        }
        __syncthreads();
        const unsigned int pref = s_bsel;
        for (int j = tid; j < nvec; j += bd) {
            float4 v = p[j];
            unsigned int kk[4] = { f2k(v.x), f2k(v.y), f2k(v.z), f2k(v.w) };
            #pragma unroll
            for (int jj = 0; jj < 4; jj++) {
                if ((kk[jj] >> 19) == pref) {
                    unsigned int pos = atomicAdd(&s_n, 1u);
                    if (pos < CAP) {
                        g_ckey[b][pos] = kk[jj];
                        g_cidx[b][pos] = (unsigned int)j * 4u + (unsigned int)jj;
                    }
                }
            }
        }
        __syncthreads();
        const unsigned int n2 = min(s_n, (unsigned int)CAP);
        unsigned int fixedval = 0, fixedmask = 0;
        if (tid == 0) { s_m = s_r; s_E = 0; }   // s_m = running rank
        __syncthreads();
        const int shifts[3] = { 11, 3, 0 };
        const int widths[3] = { 8, 8, 3 };
        for (int rr = 0; rr < 3; rr++) {
            const int s = shifts[rr];
            const unsigned int mw = (1u << widths[rr]) - 1u;
            for (int j = tid; j < 256; j += bd) sh[j] = 0;
            __syncthreads();
            for (unsigned int j = tid; j < n2; j += bd) {
                unsigned int low = g_ckey[b][j] & 0x7FFFFu;
                if ((low & fixedmask) == fixedval)
                    atomicAdd(&sh[(low >> s) & mw], 1u);
            }
            __syncthreads();
            if (tid == 0) {
                unsigned int cum = 0, rank = s_m, sel = 0;
                for (int d = (int)mw; d >= 0; d--) {
                    unsigned int c = sh[d];
                    if (cum + c >= rank) { sel = (unsigned int)d; s_m = rank - cum; s_E = c; break; }
                    cum += c;
                }
                s_thr = sel;   // broadcast digit via s_thr
            }
            __syncthreads();
            fixedval  |= s_thr << s;
            fixedmask |= mw    << s;
            __syncthreads();
        }
        const unsigned int thr   = (pref << 19) | fixedval;
        const unsigned int extra = s_m;
        const unsigned int E     = s_E;
        if (extra < E) {
            unsigned int* eq = sh;
            for (unsigned int j = tid; j < n2; j += bd) {
                if (g_ckey[b][j] == thr) {
                    unsigned int pos = atomicAdd(&s_neq, 1u);
                    if (pos < SBUF) eq[pos] = g_cidx[b][j];
                }
            }
            __syncthreads();
            unsigned int ne = min(s_neq, (unsigned int)SBUF);
            for (unsigned int j = tid; j < ne; j += bd) {
                unsigned int me = eq[j], c2 = 0;
                for (unsigned int t = 0; t < ne; t++) c2 += (eq[t] <= me);
                if (c2 == extra) s_cut = me;
            }
            __syncthreads();
        }
        const unsigned int cut = s_cut;
        // full rewrite of this row
        for (int j = tid; j < nvec; j += bd) {
            float4 v = p[j];
            unsigned int base = (unsigned int)j * 4u;
            unsigned int k0 = f2k(v.x), k1 = f2k(v.y), k2 = f2k(v.z), k3 = f2k(v.w);
            float4 o;
            o.x = (k0 > thr || (k0 == thr && base + 0u <= cut)) ? v.x : 0.0f;
            o.y = (k1 > thr || (k1 == thr && base + 1u <= cut)) ? v.y : 0.0f;
            o.z = (k2 > thr || (k2 == thr && base + 2u <= cut)) ? v.z : 0.0f;
            o.w = (k3 > thr || (k3 == thr && base + 3u <= cut)) ? v.w : 0.0f;
            q[j] = o;
        }
    }
}

// ============================== HOST =======================================

extern "C" void kernel_launch(void* const* d_in, const int* in_sizes, int n_in,
                              void* d_out, int out_size) {
    (void)n_in; (void)out_size;
    const int total = in_sizes[0];           // 33,554,432
    const int N     = total / NBATCH;        // 4,194,304
    int k = (int)((double)N * 0.1);          // 419,430
    if (k < 1) k = 1;
    const int nvec = N / 4;                  // 1,048,576 float4 per row

    const float4* in  = (const float4*)d_in[0];
    float4*       out = (float4*)d_out;

    dim3 gA(256, NBATCH);                    // fastest measured streaming grid
    k_all<<<gA, 512>>>(in, out, nvec, k);
}